// round 6
// baseline (speedup 1.0000x reference)
#include <cuda_runtime.h>
#include <cuda_bf16.h>

// Gridworld env step: warp-per-4-envs, fully interleaved chains.
// Round 1: scalars for all 4 envs + delta table + lut (all parallel loads).
// Round 2: both candidate windows for all 4 envs (32 parallel loads/lane).
//
// Inputs (metadata order):
//   0 grids (N,64,64) f32 | 1 energy (N,) f32 | 2 lut (5,) f32
//   3 agent_x (N,) i32 | 4 agent_y (N,) i32 | 5 agent_steps (unused)
//   6 actions (N,) i32 | 7 action_deltas (9,2) i32
// Output: obs (N, 6, 11, 11) f32

#define HW   64
#define VIEW 11
#define RAD  5
#define CELLS 121            // 11*11
#define OBS_PER_ENV 726      // 6*121
#define WARPS_PER_BLOCK 4
#define ENVS_PER_WARP 4
#define ENVS_PER_BLOCK (WARPS_PER_BLOCK * ENVS_PER_WARP)  // 16

__global__ __launch_bounds__(128)
void env_step_kernel(const float* __restrict__ grids,
                     const float* __restrict__ energy_in,
                     const float* __restrict__ lut,
                     const int*   __restrict__ agent_x,
                     const int*   __restrict__ agent_y,
                     const int*   __restrict__ actions,
                     const int*   __restrict__ deltas,
                     float*       __restrict__ out,
                     int n_envs)
{
    const int warp = (blockIdx.x * WARPS_PER_BLOCK) + (threadIdx.x >> 5);
    const int lane = threadIdx.x & 31;
    const int env0 = warp * ENVS_PER_WARP;
    if (env0 >= n_envs) return;

    // ---- ROUND 1: all independent loads for all 4 envs + shared tables ----
    const int dval = (lane < 18) ? __ldg(deltas + lane) : 0;   // whole delta table
    const float l0 = __ldg(lut + 0);
    const float l1 = __ldg(lut + 1);
    const float l2 = __ldg(lut + 2);
    const float l3 = __ldg(lut + 3);

    int   a[ENVS_PER_WARP], y0[ENVS_PER_WARP], x0[ENVS_PER_WARP];
    float en[ENVS_PER_WARP];
    #pragma unroll
    for (int e = 0; e < ENVS_PER_WARP; e++) {
        a[e]  = __ldg(actions   + env0 + e);
        y0[e] = __ldg(agent_y   + env0 + e);
        x0[e] = __ldg(agent_x   + env0 + e);
        en[e] = __ldg(energy_in + env0 + e);
    }

    int nyc[ENVS_PER_WARP], nxc[ENVS_PER_WARP];
    #pragma unroll
    for (int e = 0; e < ENVS_PER_WARP; e++) {
        const int dy = __shfl_sync(0xffffffffu, dval, 2 * a[e]);
        const int dx = __shfl_sync(0xffffffffu, dval, 2 * a[e] + 1);
        nyc[e] = min(max(y0[e] + dy, 0), HW - 1);
        nxc[e] = min(max(x0[e] + dx, 0), HW - 1);
    }

    // ---- ROUND 2: both candidate windows for all 4 envs (32 loads/lane) ----
    float wm[ENVS_PER_WARP][4], ws[ENVS_PER_WARP][4];
    #pragma unroll
    for (int j = 0; j < 4; j++) {
        const int c  = lane + 32 * j;        // cell 0..127
        const int wy = c / VIEW - RAD;
        const int wx = c % VIEW - RAD;
        #pragma unroll
        for (int e = 0; e < ENVS_PER_WARP; e++) {
            const float* __restrict__ g = grids + (size_t)(env0 + e) * (HW * HW);
            {   // move-window
                const int gy = nyc[e] + wy, gx = nxc[e] + wx;
                float v = 1.0f;
                if (c < CELLS && (unsigned)gy < (unsigned)HW && (unsigned)gx < (unsigned)HW)
                    v = __ldg(g + gy * HW + gx);
                wm[e][j] = v;
            }
            {   // stay-window
                const int gy = y0[e] + wy, gx = x0[e] + wx;
                float v = 1.0f;
                if (c < CELLS && (unsigned)gy < (unsigned)HW && (unsigned)gx < (unsigned)HW)
                    v = __ldg(g + gy * HW + gx);
                ws[e][j] = v;
            }
        }
    }

    // ---- resolve + emit, per env ----
    #pragma unroll
    for (int e = 0; e < ENVS_PER_WARP; e++) {
        // center cell c=60 lives in lane 28, j=1; always in-bounds
        const float tgt   = __shfl_sync(0xffffffffu, wm[e][1], 28);
        const float stayc = __shfl_sync(0xffffffffu, ws[e][1], 28);

        const bool  blocked  = (tgt == 1.0f);
        const float cell     = blocked ? stayc : tgt;
        const bool  food     = (cell == 2.0f);
        const bool  poison   = (cell == 3.0f);
        const bool  consumed = food | poison;
        const float reward   = (food ? 10.0f : 0.0f) - (poison ? 10.0f : 0.0f);
        const float energy   = en[e] - 1.0f + reward;

        float* __restrict__ o = out + (size_t)(env0 + e) * OBS_PER_ENV;
        #pragma unroll
        for (int j = 0; j < 4; j++) {
            const int c = lane + 32 * j;
            if (c < CELLS) {
                float v = blocked ? ws[e][j] : wm[e][j];
                if (consumed && c == 60) v = 0.0f;    // landed cell -> EMPTY
                const int   vi = (int)v;
                const float lv = (vi == 0) ? l0 : (vi == 1) ? l1 : (vi == 2) ? l2 : l3;
                o[0 * CELLS + c] = (v == 2.0f) ? 1.0f : 0.0f;
                o[1 * CELLS + c] = (v == 3.0f) ? 1.0f : 0.0f;
                o[2 * CELLS + c] = (v == 1.0f) ? 1.0f : 0.0f;
                o[3 * CELLS + c] = lv;
                o[4 * CELLS + c] = v;
                o[5 * CELLS + c] = energy;
            }
        }
    }
}

extern "C" void kernel_launch(void* const* d_in, const int* in_sizes, int n_in,
                              void* d_out, int out_size)
{
    const float* grids   = (const float*)d_in[0];
    const float* energy  = (const float*)d_in[1];
    const float* lut     = (const float*)d_in[2];
    const int*   ax      = (const int*)  d_in[3];
    const int*   ay      = (const int*)  d_in[4];
    // d_in[5] agent_steps unused
    const int*   actions = (const int*)  d_in[6];
    const int*   deltas  = (const int*)  d_in[7];
    float*       out     = (float*)      d_out;

    const int n_envs = in_sizes[1];
    const int blocks = (n_envs + ENVS_PER_BLOCK - 1) / ENVS_PER_BLOCK;

    env_step_kernel<<<blocks, 128>>>(grids, energy, lut, ax, ay, actions, deltas, out, n_envs);
}

// round 7
// speedup vs baseline: 1.0029x; 1.0029x over previous
#include <cuda_runtime.h>
#include <cuda_bf16.h>

// Gridworld env step: warp-per-env, union-window staged in shared memory.
// Gather = 48 float4 tasks (2 predicated LDG.128 per env) covering the 12x12
// union of the stay- and move-candidate 11x11 windows. Move resolution (tgt,
// stay-center) reads from smem, so there is exactly ONE global gather round.
//
// Inputs (metadata order):
//   0 grids (N,64,64) f32 | 1 energy (N,) f32 | 2 lut (5,) f32
//   3 agent_x (N,) i32 | 4 agent_y (N,) i32 | 5 agent_steps (unused)
//   6 actions (N,) i32 | 7 action_deltas (9,2) i32
// Output: obs (N, 6, 11, 11) f32

#define HW   64
#define VIEW 11
#define RAD  5
#define CELLS 121
#define OBS_PER_ENV 726
#define WARPS_PER_BLOCK 8

__global__ __launch_bounds__(256)
void env_step_kernel(const float* __restrict__ grids,
                     const float* __restrict__ energy_in,
                     const float* __restrict__ lut,
                     const int*   __restrict__ agent_x,
                     const int*   __restrict__ agent_y,
                     const int*   __restrict__ actions,
                     const int*   __restrict__ deltas,
                     float*       __restrict__ out,
                     int n_envs)
{
    __shared__ float s_win[WARPS_PER_BLOCK][12][16];

    const int wib  = threadIdx.x >> 5;
    const int lane = threadIdx.x & 31;
    const int env  = blockIdx.x * WARPS_PER_BLOCK + wib;
    if (env >= n_envs) return;

    float (* __restrict__ win)[16] = s_win[wib];
    const float* __restrict__ g = grids + (size_t)env * (HW * HW);

    // ---- ROUND 1: independent scalar loads ----
    const int   a   = __ldg(actions   + env);
    const int   y0  = __ldg(agent_y   + env);
    const int   x0  = __ldg(agent_x   + env);
    const float en0 = __ldg(energy_in + env);
    const int   dval = (lane < 18) ? __ldg(deltas + lane) : 0;
    const float l0 = __ldg(lut + 0);
    const float l1 = __ldg(lut + 1);
    const float l2 = __ldg(lut + 2);
    const float l3 = __ldg(lut + 3);

    const int dy = __shfl_sync(0xffffffffu, dval, 2 * a);
    const int dx = __shfl_sync(0xffffffffu, dval, 2 * a + 1);

    const int nyc = min(max(y0 + dy, 0), HW - 1);   // candidate move pos
    const int nxc = min(max(x0 + dx, 0), HW - 1);

    // union-window origin (covers both 11x11 windows; extent <= 12x12)
    const int by = min(y0, nyc) - RAD;                    // may be <0
    const int bx = min(x0, nxc) - RAD;
    const int cb = min(max(bx, 0) & ~3, HW - 16);         // 16B-aligned col base

    // ---- ROUND 2: single gather — 48 float4 tasks into smem ----
    #pragma unroll
    for (int it = 0; it < 2; it++) {
        const int task = lane + 32 * it;
        if (task < 48) {
            const int r  = task >> 2;          // union row 0..11
            const int s  = task & 3;           // 16B segment 0..3
            const int gy = by + r;
            if ((unsigned)gy < (unsigned)HW) {
                const float4 v = *(const float4*)(g + gy * HW + cb + 4 * s);
                *(float4*)&win[r][4 * s] = v;
            }
        }
    }
    __syncwarp();

    // ---- resolve move from smem (broadcast LDS, no extra global round) ----
    const float tgt   = win[nyc - by][nxc - cb];
    const float stayc = win[y0  - by][x0  - cb];

    const bool  blocked  = (tgt == 1.0f);
    const int   ny = blocked ? y0 : nyc;
    const int   nx = blocked ? x0 : nxc;
    const float cell     = blocked ? stayc : tgt;
    const bool  food     = (cell == 2.0f);
    const bool  poison   = (cell == 3.0f);
    const bool  consumed = food | poison;
    const float reward   = (food ? 10.0f : 0.0f) - (poison ? 10.0f : 0.0f);
    const float energy   = en0 - 1.0f + reward;

    // ---- emit 6 channels, cell-major (coalesced 128B stores per channel) ----
    float* __restrict__ o = out + (size_t)env * OBS_PER_ENV;
    #pragma unroll
    for (int j = 0; j < 4; j++) {
        const int c = lane + 32 * j;
        if (c < CELLS) {
            const int wy = c / VIEW - RAD;
            const int wx = c % VIEW - RAD;
            const int gy = ny + wy;
            const int gx = nx + wx;
            float v = 1.0f;                                   // WALL padding
            if ((unsigned)gy < (unsigned)HW && (unsigned)gx < (unsigned)HW)
                v = win[gy - by][gx - cb];
            if (consumed && c == 60) v = 0.0f;                // landed -> EMPTY
            const int   vi = (int)v;
            const float lv = (vi == 0) ? l0 : (vi == 1) ? l1 : (vi == 2) ? l2 : l3;
            o[0 * CELLS + c] = (v == 2.0f) ? 1.0f : 0.0f;
            o[1 * CELLS + c] = (v == 3.0f) ? 1.0f : 0.0f;
            o[2 * CELLS + c] = (v == 1.0f) ? 1.0f : 0.0f;
            o[3 * CELLS + c] = lv;
            o[4 * CELLS + c] = v;
            o[5 * CELLS + c] = energy;
        }
    }
}

extern "C" void kernel_launch(void* const* d_in, const int* in_sizes, int n_in,
                              void* d_out, int out_size)
{
    const float* grids   = (const float*)d_in[0];
    const float* energy  = (const float*)d_in[1];
    const float* lut     = (const float*)d_in[2];
    const int*   ax      = (const int*)  d_in[3];
    const int*   ay      = (const int*)  d_in[4];
    // d_in[5] agent_steps unused
    const int*   actions = (const int*)  d_in[6];
    const int*   deltas  = (const int*)  d_in[7];
    float*       out     = (float*)      d_out;

    const int n_envs = in_sizes[1];
    const int blocks = (n_envs + WARPS_PER_BLOCK - 1) / WARPS_PER_BLOCK;

    env_step_kernel<<<blocks, 256>>>(grids, energy, lut, ax, ay, actions, deltas, out, n_envs);
}

// round 8
// speedup vs baseline: 1.0239x; 1.0209x over previous
#include <cuda_runtime.h>
#include <cuda_bf16.h>

// Gridworld env step: warp-per-env union-window gather (R7) + smem-staged,
// 16B-aligned vectorized output stores.
// Old store path: 24 misaligned STG.32/env -> 48 split wavefronts w/ partial
// sectors. New: stage 726 floats/env in smem, block-copy 8 envs (23232B,
// 16B-aligned dense) as STG.128 -> 23 full-line wavefronts/env.
//
// Inputs (metadata order):
//   0 grids (N,64,64) f32 | 1 energy (N,) f32 | 2 lut (5,) f32
//   3 agent_x (N,) i32 | 4 agent_y (N,) i32 | 5 agent_steps (unused)
//   6 actions (N,) i32 | 7 action_deltas (9,2) i32
// Output: obs (N, 6, 11, 11) f32

#define HW   64
#define VIEW 11
#define RAD  5
#define CELLS 121
#define OBS_PER_ENV 726
#define WPB 8               // warps (=envs) per block

__global__ __launch_bounds__(256)
void env_step_kernel(const float* __restrict__ grids,
                     const float* __restrict__ energy_in,
                     const float* __restrict__ lut,
                     const int*   __restrict__ agent_x,
                     const int*   __restrict__ agent_y,
                     const int*   __restrict__ actions,
                     const int*   __restrict__ deltas,
                     float*       __restrict__ out,
                     int n_envs)
{
    __shared__ float s_win[WPB][12][16];
    __shared__ __align__(16) float s_obs[WPB * OBS_PER_ENV];   // 23232 B

    const int wib   = threadIdx.x >> 5;
    const int lane  = threadIdx.x & 31;
    const int env0  = blockIdx.x * WPB;
    const int env   = env0 + wib;

    if (env < n_envs) {
        float (* __restrict__ win)[16] = s_win[wib];
        const float* __restrict__ g = grids + (size_t)env * (HW * HW);

        // ---- ROUND 1: independent scalar loads ----
        const int   a   = __ldg(actions   + env);
        const int   y0  = __ldg(agent_y   + env);
        const int   x0  = __ldg(agent_x   + env);
        const float en0 = __ldg(energy_in + env);
        const int   dval = (lane < 18) ? __ldg(deltas + lane) : 0;
        const float l0 = __ldg(lut + 0);
        const float l1 = __ldg(lut + 1);
        const float l2 = __ldg(lut + 2);
        const float l3 = __ldg(lut + 3);

        const int dy = __shfl_sync(0xffffffffu, dval, 2 * a);
        const int dx = __shfl_sync(0xffffffffu, dval, 2 * a + 1);

        const int nyc = min(max(y0 + dy, 0), HW - 1);
        const int nxc = min(max(x0 + dx, 0), HW - 1);

        // union-window origin (covers both 11x11 windows; extent <= 12x12)
        const int by = min(y0, nyc) - RAD;
        const int bx = min(x0, nxc) - RAD;
        const int cb = min(max(bx, 0) & ~3, HW - 16);     // 16B-aligned col base

        // ---- ROUND 2: single gather — 48 float4 tasks into smem ----
        #pragma unroll
        for (int it = 0; it < 2; it++) {
            const int task = lane + 32 * it;
            if (task < 48) {
                const int r  = task >> 2;
                const int s  = task & 3;
                const int gy = by + r;
                if ((unsigned)gy < (unsigned)HW) {
                    const float4 v = *(const float4*)(g + gy * HW + cb + 4 * s);
                    *(float4*)&win[r][4 * s] = v;
                }
            }
        }
        __syncwarp();

        // ---- resolve move from smem ----
        const float tgt   = win[nyc - by][nxc - cb];
        const float stayc = win[y0  - by][x0  - cb];

        const bool  blocked  = (tgt == 1.0f);
        const int   ny = blocked ? y0 : nyc;
        const int   nx = blocked ? x0 : nxc;
        const float cell     = blocked ? stayc : tgt;
        const bool  food     = (cell == 2.0f);
        const bool  poison   = (cell == 3.0f);
        const bool  consumed = food | poison;
        const float reward   = (food ? 10.0f : 0.0f) - (poison ? 10.0f : 0.0f);
        const float energy   = en0 - 1.0f + reward;

        // ---- emit 6 channels into smem staging ----
        float* __restrict__ so = s_obs + wib * OBS_PER_ENV;
        #pragma unroll
        for (int j = 0; j < 4; j++) {
            const int c = lane + 32 * j;
            if (c < CELLS) {
                const int wy = c / VIEW - RAD;
                const int wx = c % VIEW - RAD;
                const int gy = ny + wy;
                const int gx = nx + wx;
                float v = 1.0f;                               // WALL padding
                if ((unsigned)gy < (unsigned)HW && (unsigned)gx < (unsigned)HW)
                    v = win[gy - by][gx - cb];
                if (consumed && c == 60) v = 0.0f;            // landed -> EMPTY
                const int   vi = (int)v;
                const float lv = (vi == 0) ? l0 : (vi == 1) ? l1 : (vi == 2) ? l2 : l3;
                so[0 * CELLS + c] = (v == 2.0f) ? 1.0f : 0.0f;
                so[1 * CELLS + c] = (v == 3.0f) ? 1.0f : 0.0f;
                so[2 * CELLS + c] = (v == 1.0f) ? 1.0f : 0.0f;
                so[3 * CELLS + c] = lv;
                so[4 * CELLS + c] = v;
                so[5 * CELLS + c] = energy;
            }
        }
    }

    __syncthreads();

    // ---- cooperative aligned block copy: smem -> gmem ----
    const int nloc = min(WPB, n_envs - env0);
    if (nloc == WPB) {
        // full block: 8*726 floats = 1452 float4, base 16B-aligned & dense
        float4* __restrict__ dst = (float4*)(out + (size_t)env0 * OBS_PER_ENV);
        const float4* __restrict__ src = (const float4*)s_obs;
        #pragma unroll
        for (int k = 0; k < 6; k++) {
            const int i = threadIdx.x + 256 * k;
            if (i < (WPB * OBS_PER_ENV) / 4)
                dst[i] = src[i];
        }
    } else if (nloc > 0) {
        // tail block: float2 (env base always 8B-aligned)
        float2* __restrict__ dst = (float2*)(out + (size_t)env0 * OBS_PER_ENV);
        const float2* __restrict__ src = (const float2*)s_obs;
        const int n2 = nloc * (OBS_PER_ENV / 2);
        for (int i = threadIdx.x; i < n2; i += 256)
            dst[i] = src[i];
    }
}

extern "C" void kernel_launch(void* const* d_in, const int* in_sizes, int n_in,
                              void* d_out, int out_size)
{
    const float* grids   = (const float*)d_in[0];
    const float* energy  = (const float*)d_in[1];
    const float* lut     = (const float*)d_in[2];
    const int*   ax      = (const int*)  d_in[3];
    const int*   ay      = (const int*)  d_in[4];
    // d_in[5] agent_steps unused
    const int*   actions = (const int*)  d_in[6];
    const int*   deltas  = (const int*)  d_in[7];
    float*       out     = (float*)      d_out;

    const int n_envs = in_sizes[1];
    const int blocks = (n_envs + WPB - 1) / WPB;

    env_step_kernel<<<blocks, 256>>>(grids, energy, lut, ax, ay, actions, deltas, out, n_envs);
}